// round 2
// baseline (speedup 1.0000x reference)
#include <cuda_runtime.h>

#define FRAME   160
#define ORDER   16
#define EPS     1e-8f
#define CH      20          // samples per lane
#define FPW     4           // frames per warp
#define WARPS   8
#define THREADS (WARPS * 32)
#define FSTRIDE 202         // floats per frame region (16 pad | 160 data | 16 pad | 10 slack)
#define PSTRIDE (FSTRIDE/2) // 101 float2-pairs per frame region
#define WSTRIDE (FPW * FSTRIDE)

typedef unsigned long long u64;

// ---- packed f32x2 helpers (Blackwell FFMA2 path: only reachable via PTX) ----
__device__ __forceinline__ u64 fma2(u64 a, u64 b, u64 c) {
    u64 d; asm("fma.rn.f32x2 %0, %1, %2, %3;" : "=l"(d) : "l"(a), "l"(b), "l"(c));
    return d;
}
__device__ __forceinline__ u64 mul2(u64 a, u64 b) {
    u64 d; asm("mul.rn.f32x2 %0, %1, %2;" : "=l"(d) : "l"(a), "l"(b));
    return d;
}
__device__ __forceinline__ u64 pack2(float lo, float hi) {
    u64 r; asm("mov.b64 %0, {%1, %2};" : "=l"(r) : "f"(lo), "f"(hi));
    return r;
}
// (hi(a), lo(b)) — misaligned pair view; resolves to register placement MOVs
__device__ __forceinline__ u64 shiftpair(u64 a, u64 b) {
    float al, ah, bl, bh;
    asm("mov.b64 {%0, %1}, %2;" : "=f"(al), "=f"(ah) : "l"(a));
    asm("mov.b64 {%0, %1}, %2;" : "=f"(bl), "=f"(bh) : "l"(b));
    u64 r; asm("mov.b64 %0, {%1, %2};" : "=l"(r) : "f"(ah), "f"(bl));
    return r;
}
__device__ __forceinline__ float hadd2(u64 v) {
    float a, b; asm("mov.b64 {%0, %1}, %2;" : "=f"(a), "=f"(b) : "l"(v));
    return a + b;
}

__global__ __launch_bounds__(THREADS, 2)
void lpc_residual_kernel(const float* __restrict__ x,
                         float* __restrict__ out,
                         int nframes)
{
    __shared__ __align__(16) float sx[WARPS * WSTRIDE];

    const int lane = threadIdx.x & 31;
    const int wid  = threadIdx.x >> 5;
    const int warpGlobal = blockIdx.x * WARPS + wid;
    const int frame0 = warpGlobal * FPW;

    float* sw  = sx + wid * WSTRIDE;
    u64*   swp = (u64*)sw;

    // ---- zero pads: per frame, floats [0,16) and [176,192) => pairs [0,8) and [88,96) ----
    {
        int f = lane >> 3;         // 0..3
        int c = lane & 7;          // 0..7
        swp[f * PSTRIDE + c]      = 0ull;
        swp[f * PSTRIDE + 88 + c] = 0ull;
    }

    // ---- stage input: 10x LDG.64 + 10x STS.64 per lane (coalesced, bank-conflict-free) ----
    {
        const float2* gx2 = (const float2*)(x + (long long)frame0 * FRAME);
        #pragma unroll
        for (int q = 0; q < 10; q++) {
            int idx = q * 32 + lane;                      // float2 chunk within warp's 320
            int f;
            if (q == 2)      f = (lane < 16) ? 0 : 1;     // only q=2 and q=7 cross a frame
            else if (q == 7) f = (lane < 16) ? 2 : 3;
            else             f = (q * 32) / 80;           // compile-time constant
            if (frame0 + f < nframes) {
                float2 v = gx2[idx];
                // shared pair index: f*101 + 8 + (idx - 80f) = idx + 8 + 21f
                swp[idx + 8 + 21 * f] = pack2(v.x, v.y);
            }
        }
    }
    __syncwarp();

    const int fl = lane >> 3;   // frame within warp (0..3)
    const int p  = lane & 7;    // sub-lane within frame (0..7)

    // U[j] = pair of floats (w[2j-16], w[2j-15]) where w[m] = x[20p + m] of this frame
    // (pads at both ends make boundaries exact zeros)
    const int ubase = fl * PSTRIDE + 10 * p;   // pair index of float (fl*202 + 20p)

    u64 U[26];
    #pragma unroll
    for (int j = 8; j < 26; j++) U[j] = swp[ubase + j];

    // SS[i] = (w[2(i-8)+1], w[2(i-8)+2]) = shiftpair(U[i], U[i+1])
    u64 SS[25];
    #pragma unroll
    for (int i = 8; i < 25; i++) SS[i] = shiftpair(U[i], U[i + 1]);

    // ---- autocorrelation: r[k] = sum_{m=0}^{19} w[m]*w[m+k], packed over m ----
    float r[ORDER + 1];
    #pragma unroll
    for (int k = 0; k <= ORDER; k++) {
        u64 acc;
        if (k & 1) acc = mul2(U[8], SS[8 + (k - 1) / 2]);
        else       acc = mul2(U[8], U[8 + k / 2]);
        #pragma unroll
        for (int j = 1; j < 10; j++) {
            u64 b = (k & 1) ? SS[8 + j + (k - 1) / 2] : U[8 + j + k / 2];
            acc = fma2(U[8 + j], b, acc);
        }
        float s = hadd2(acc);
        s += __shfl_xor_sync(0xFFFFFFFFu, s, 1);
        s += __shfl_xor_sync(0xFFFFFFFFu, s, 2);
        s += __shfl_xor_sync(0xFFFFFFFFu, s, 4);
        r[k] = s;
    }

    // ---- Levinson-Durbin, fully unrolled, fast divide ----
    float a[ORDER + 1];
    a[0] = 1.0f;
    float e = (r[0] != 0.0f) ? r[0] : EPS;
    #pragma unroll
    for (int i = 1; i <= ORDER; i++) {
        float acc = r[i];
        #pragma unroll
        for (int j = 1; j < i; j++)
            acc = fmaf(-a[j], r[i - j], acc);
        float kk = __fdividef(acc, e);
        float tn[ORDER + 1];
        #pragma unroll
        for (int j = 1; j < i; j++)
            tn[j] = fmaf(-kk, a[i - j], a[j]);
        #pragma unroll
        for (int j = 1; j < i; j++)
            a[j] = tn[j];
        a[i] = kk;
        e = fmaxf(e - kk * kk * e, EPS);
    }

    // ---- FIR: res[n] = sum_{k=0}^{16} a[k] * w[n-k]  (w[neg] hits zero pad / prev samples) ----
    #pragma unroll
    for (int j = 0; j < 8; j++) U[j] = swp[ubase + j];
    #pragma unroll
    for (int i = 0; i < 8; i++) SS[i] = shiftpair(U[i], U[i + 1]);

    u64 aP[ORDER + 1];
    #pragma unroll
    for (int k = 1; k <= ORDER; k++) aP[k] = pack2(a[k], a[k]);

    float* go = out + (long long)(frame0 + fl) * FRAME + 20 * p;
    const bool wr = (frame0 + fl) < nframes;

    #pragma unroll
    for (int t2 = 0; t2 < 5; t2++) {
        u64 accs[2];
        #pragma unroll
        for (int h = 0; h < 2; h++) {
            int t = 2 * t2 + h;            // output pair (res[2t], res[2t+1])
            u64 acc = U[8 + t];            // a[0] = 1 term
            #pragma unroll
            for (int k = 1; k <= ORDER; k++) {
                u64 b = (k & 1) ? SS[8 + t - (k + 1) / 2] : U[8 + t - k / 2];
                acc = fma2(aP[k], b, acc);
            }
            accs[h] = acc;
        }
        if (wr)
            asm volatile("st.global.v2.b64 [%0], {%1, %2};"
                         :: "l"(go + 4 * t2), "l"(accs[0]), "l"(accs[1]) : "memory");
    }
}

extern "C" void kernel_launch(void* const* d_in, const int* in_sizes, int n_in,
                              void* d_out, int out_size)
{
    const float* x = (const float*)d_in[0];
    float* out = (float*)d_out;

    long long total = in_sizes[0];
    int nframes = (int)(total / FRAME);           // 128000 for the given shape
    int warpsNeeded = (nframes + FPW - 1) / FPW;
    int blocks = (warpsNeeded + WARPS - 1) / WARPS;

    lpc_residual_kernel<<<blocks, THREADS>>>(x, out, nframes);
}

// round 3
// speedup vs baseline: 1.1553x; 1.1553x over previous
#include <cuda_runtime.h>

#define FRAME   160
#define ORDER   16
#define EPS     1e-8f
#define FPW     4                 // frames per warp
#define WARPS   8
#define THREADS 256
#define FPB     (WARPS * FPW)     // 32 frames per block
#define FSTRIDE 198               // floats per frame region: 16 pad | 160 | 16 pad | 6 slack
#define PSTRIDE 99                // float2 pairs per frame region (odd -> conflict-free LDS.64)

typedef unsigned long long u64;

__device__ __forceinline__ u64 pack2(float lo, float hi) {
    u64 r; asm("mov.b64 %0, {%1, %2};" : "=l"(r) : "f"(lo), "f"(hi));
    return r;
}

__global__ __launch_bounds__(THREADS, 3)
void lpc_residual_kernel(const float* __restrict__ x,
                         float* __restrict__ out,
                         int nframes)
{
    __shared__ __align__(16) float sx[WARPS * FPW * FSTRIDE];   // 25344 B
    __shared__ float rS[FPB][17];                               // autocorr per frame
    __shared__ float aS[FPB][17];                               // LPC coeffs per frame

    const int lane   = threadIdx.x & 31;
    const int wid    = threadIdx.x >> 5;
    const int frame0 = blockIdx.x * FPB + wid * FPW;            // this warp's first frame

    float* sw  = sx + wid * FPW * FSTRIDE;
    u64*   swp = (u64*)sw;

    // ---- zero pads: per frame, floats [0,16) and [176,192) => pairs [0,8) and [88,96) ----
    {
        int f = lane >> 3, c = lane & 7;
        swp[f * PSTRIDE + c]      = 0ull;
        swp[f * PSTRIDE + 88 + c] = 0ull;
    }

    // ---- stage input: 10x LDG.64 + 10x STS.64 per lane, coalesced & conflict-free ----
    {
        const float2* gx2 = (const float2*)(x + (long long)frame0 * FRAME);
        #pragma unroll
        for (int q = 0; q < 10; q++) {
            int idx = q * 32 + lane;               // float2 index within warp's 320
            int f;
            if (q == 2)      f = (lane < 16) ? 0 : 1;   // frame boundary crossings
            else if (q == 7) f = (lane < 16) ? 2 : 3;
            else             f = (q * 32) / 80;         // compile-time constant
            if (frame0 + f < nframes) {
                float2 v = gx2[idx];
                // shared pair index: f*99 + 8 + (idx - 80f) = idx + 8 + 19f
                swp[idx + 8 + 19 * f] = pack2(v.x, v.y);
            }
        }
    }
    __syncwarp();   // warp only reads its own staged frames below

    const int fl = lane >> 3;               // frame within warp (0..3)
    const int p  = lane & 7;                // sub-lane within frame (0..7)
    const int myFrame = wid * FPW + fl;     // frame index within block
    // pair index of float w[0] = x[20p] of this frame (float idx fl*198 + 16 + 20p)
    const int ubase = fl * PSTRIDE + 8 + 10 * p;
    const float2* swp2 = (const float2*)swp;

    // ---- load autocorr window w[0..35] via 18 LDS.64 (tail hits zero pad) ----
    float w[36];
    #pragma unroll
    for (int j = 0; j < 18; j++) {
        float2 t = swp2[ubase + j];
        w[2 * j] = t.x; w[2 * j + 1] = t.y;
    }

    // ---- autocorrelation: r[k] = sum_m w[m] w[m+k]; butterfly reduce over 8 lanes ----
    #pragma unroll
    for (int k = 0; k <= ORDER; k++) {
        float acc = 0.0f;
        #pragma unroll
        for (int m = 0; m < 20; m++)
            acc = fmaf(w[m], w[m + k], acc);
        acc += __shfl_xor_sync(0xFFFFFFFFu, acc, 1);
        acc += __shfl_xor_sync(0xFFFFFFFFu, acc, 2);
        acc += __shfl_xor_sync(0xFFFFFFFFu, acc, 4);
        if (p == 0) rS[myFrame][k] = acc;   // store immediately: no live r[] array
    }
    __syncthreads();

    // ---- Levinson-Durbin: warp 0 only, one frame per lane (8x fewer issue slots) ----
    if (wid == 0) {
        float rr[ORDER + 1];
        #pragma unroll
        for (int k = 0; k <= ORDER; k++) rr[k] = rS[lane][k];

        float a[ORDER + 1];
        a[0] = 1.0f;
        float e = (rr[0] != 0.0f) ? rr[0] : EPS;
        #pragma unroll
        for (int i = 1; i <= ORDER; i++) {
            float acc = rr[i];
            #pragma unroll
            for (int j = 1; j < i; j++)
                acc = fmaf(-a[j], rr[i - j], acc);
            float kk = __fdividef(acc, e);
            float tn[ORDER + 1];
            #pragma unroll
            for (int j = 1; j < i; j++)
                tn[j] = fmaf(-kk, a[i - j], a[j]);
            #pragma unroll
            for (int j = 1; j < i; j++)
                a[j] = tn[j];
            a[i] = kk;
            // e*(1-k^2) = e - k*(k*e) = e - k*acc  (k*e == acc up to rounding)
            e = fmaxf(fmaf(-kk, acc, e), EPS);
        }
        #pragma unroll
        for (int k = 1; k <= ORDER; k++) aS[lane][k] = a[k];
    }
    __syncthreads();

    // ---- broadcast coeffs (8-lane broadcast per frame, conflict-free) ----
    float a[ORDER + 1];
    #pragma unroll
    for (int k = 1; k <= ORDER; k++) a[k] = aS[myFrame][k];

    // ---- history window w[-16..-1] via 8 LDS.64 (front pad / previous lane's samples) ----
    float v[16];
    #pragma unroll
    for (int j = 0; j < 8; j++) {
        float2 t = swp2[ubase - 8 + j];
        v[2 * j] = t.x; v[2 * j + 1] = t.y;
    }

    // ---- FIR: res[n] = w[n] + sum_{k=1}^{16} a[k] * w[n-k]; store as float4 groups ----
    const bool wr = (frame0 + fl) < nframes;
    float4* go4 = (float4*)(out + (long long)(frame0 + fl) * FRAME + 20 * p);

    #pragma unroll
    for (int g = 0; g < 5; g++) {
        float res[4];
        #pragma unroll
        for (int h = 0; h < 4; h++) {
            int m = 4 * g + h;
            float s = w[m];                    // a[0] = 1 term
            #pragma unroll
            for (int k = 1; k <= ORDER; k++) {
                int i = m - k;
                s = fmaf(a[k], (i >= 0) ? w[i] : v[16 + i], s);
            }
            res[h] = s;
        }
        if (wr) go4[g] = make_float4(res[0], res[1], res[2], res[3]);
    }
}

extern "C" void kernel_launch(void* const* d_in, const int* in_sizes, int n_in,
                              void* d_out, int out_size)
{
    const float* x = (const float*)d_in[0];
    float* out = (float*)d_out;

    long long total = in_sizes[0];
    int nframes = (int)(total / FRAME);                 // 128000 for the given shape
    int blocks  = (nframes + FPB - 1) / FPB;            // 4000

    lpc_residual_kernel<<<blocks, THREADS>>>(x, out, nframes);
}

// round 4
// speedup vs baseline: 1.2677x; 1.0974x over previous
#include <cuda_runtime.h>

#define FRAME   160
#define ORDER   16
#define EPS     1e-8f
#define FPW     4                 // frames per warp
#define WARPS   8
#define THREADS 256
#define FPB     (WARPS * FPW)     // 32 frames per block
#define FSTRIDE 198               // floats per frame region: 16 pad | 160 | 16 pad | 6 slack
#define PSTRIDE 99                // float2 pairs per frame region (odd -> conflict-free LDS.64)

typedef unsigned long long u64;

__device__ __forceinline__ u64 pack2(float lo, float hi) {
    u64 r; asm("mov.b64 %0, {%1, %2};" : "=l"(r) : "f"(lo), "f"(hi));
    return r;
}

__global__ __launch_bounds__(THREADS, 4)
void lpc_residual_kernel(const float* __restrict__ x,
                         float* __restrict__ out,
                         int nframes)
{
    __shared__ __align__(16) float sx[WARPS * FPW * FSTRIDE];   // 25344 B
    __shared__ float rH[2][FPB][17];    // two 4-lane autocorr partials per frame
    __shared__ float aS[FPB][17];       // LPC coeffs per frame

    const int lane   = threadIdx.x & 31;
    const int wid    = threadIdx.x >> 5;
    const int frame0 = blockIdx.x * FPB + wid * FPW;            // this warp's first frame

    float* sw  = sx + wid * FPW * FSTRIDE;
    u64*   swp = (u64*)sw;

    // ---- zero pads: per frame, floats [0,16) and [176,192) => pairs [0,8) and [88,96) ----
    {
        int f = lane >> 3, c = lane & 7;
        swp[f * PSTRIDE + c]      = 0ull;
        swp[f * PSTRIDE + 88 + c] = 0ull;
    }

    // ---- stage input: 10x LDG.64 + 10x STS.64 per lane, coalesced & conflict-free ----
    {
        const float2* gx2 = (const float2*)(x + (long long)frame0 * FRAME);
        #pragma unroll
        for (int q = 0; q < 10; q++) {
            int idx = q * 32 + lane;               // float2 index within warp's 320
            int f;
            if (q == 2)      f = (lane < 16) ? 0 : 1;   // frame boundary crossings
            else if (q == 7) f = (lane < 16) ? 2 : 3;
            else             f = (q * 32) / 80;         // compile-time constant
            if (frame0 + f < nframes) {
                float2 v = gx2[idx];
                // shared pair index: f*99 + 8 + (idx - 80f) = idx + 8 + 19f
                swp[idx + 8 + 19 * f] = pack2(v.x, v.y);
            }
        }
    }
    __syncwarp();   // warp only reads its own staged frames below

    const int fl = lane >> 3;               // frame within warp (0..3)
    const int p  = lane & 7;                // sub-lane within frame (0..7)
    const int myFrame = wid * FPW + fl;     // frame index within block
    // pair index of float w[0] = x[20p] of this frame (float idx fl*198 + 16 + 20p)
    const int ubase = fl * PSTRIDE + 8 + 10 * p;
    const float2* swp2 = (const float2*)swp;

    // ---- load autocorr window w[0..35] via 18 LDS.64 (tail hits zero pad) ----
    float w[36];
    #pragma unroll
    for (int j = 0; j < 18; j++) {
        float2 t = swp2[ubase + j];
        w[2 * j] = t.x; w[2 * j + 1] = t.y;
    }

    // ---- autocorrelation: r[k] = sum_m w[m] w[m+k]; 2-stage butterfly -> two partials ----
    #pragma unroll
    for (int k = 0; k <= ORDER; k++) {
        float acc = 0.0f;
        #pragma unroll
        for (int m = 0; m < 20; m++)
            acc = fmaf(w[m], w[m + k], acc);
        acc += __shfl_xor_sync(0xFFFFFFFFu, acc, 1);
        acc += __shfl_xor_sync(0xFFFFFFFFu, acc, 2);
        if ((p & 3) == 0) rH[p >> 2][myFrame][k] = acc;   // lanes p=0,4 store partials
    }
    __syncthreads();

    // ---- Levinson-Durbin: warp 0 only, one frame per lane ----
    if (wid == 0) {
        float rr[ORDER + 1];
        #pragma unroll
        for (int k = 0; k <= ORDER; k++)
            rr[k] = rH[0][lane][k] + rH[1][lane][k];

        float a[ORDER + 1];
        a[0] = 1.0f;
        float e = (rr[0] != 0.0f) ? rr[0] : EPS;
        #pragma unroll
        for (int i = 1; i <= ORDER; i++) {
            float acc = rr[i];
            #pragma unroll
            for (int j = 1; j < i; j++)
                acc = fmaf(-a[j], rr[i - j], acc);
            float kk = __fdividef(acc, e);
            float tn[ORDER + 1];
            #pragma unroll
            for (int j = 1; j < i; j++)
                tn[j] = fmaf(-kk, a[i - j], a[j]);
            #pragma unroll
            for (int j = 1; j < i; j++)
                a[j] = tn[j];
            a[i] = kk;
            // e*(1-k^2) = e - k*(k*e) = e - k*acc  (k*e == acc up to rounding)
            e = fmaxf(fmaf(-kk, acc, e), EPS);
        }
        #pragma unroll
        for (int k = 1; k <= ORDER; k++) aS[lane][k] = a[k];
    }
    __syncthreads();

    // ---- broadcast coeffs (8-lane broadcast per frame, conflict-free) ----
    float a[ORDER + 1];
    #pragma unroll
    for (int k = 1; k <= ORDER; k++) a[k] = aS[myFrame][k];

    // ---- history window w[-16..-1] via 8 LDS.64 (front pad / previous lane's samples) ----
    float v[16];
    #pragma unroll
    for (int j = 0; j < 8; j++) {
        float2 t = swp2[ubase - 8 + j];
        v[2 * j] = t.x; v[2 * j + 1] = t.y;
    }

    // ---- FIR: res[n] = w[n] + sum_{k=1}^{16} a[k] * w[n-k]; store as float4 groups ----
    const bool wr = (frame0 + fl) < nframes;
    float4* go4 = (float4*)(out + (long long)(frame0 + fl) * FRAME + 20 * p);

    #pragma unroll
    for (int g = 0; g < 5; g++) {
        float res[4];
        #pragma unroll
        for (int h = 0; h < 4; h++) {
            int m = 4 * g + h;
            float s = w[m];                    // a[0] = 1 term
            #pragma unroll
            for (int k = 1; k <= ORDER; k++) {
                int i = m - k;
                s = fmaf(a[k], (i >= 0) ? w[i] : v[16 + i], s);
            }
            res[h] = s;
        }
        if (wr) go4[g] = make_float4(res[0], res[1], res[2], res[3]);
    }
}

extern "C" void kernel_launch(void* const* d_in, const int* in_sizes, int n_in,
                              void* d_out, int out_size)
{
    const float* x = (const float*)d_in[0];
    float* out = (float*)d_out;

    long long total = in_sizes[0];
    int nframes = (int)(total / FRAME);                 // 128000 for the given shape
    int blocks  = (nframes + FPB - 1) / FPB;            // 4000

    lpc_residual_kernel<<<blocks, THREADS>>>(x, out, nframes);
}

// round 5
// speedup vs baseline: 1.3112x; 1.0343x over previous
#include <cuda_runtime.h>

#define FRAME   160
#define ORDER   16
#define EPS     1e-8f
#define FPW     4                 // frames per warp
#define WARPS   4
#define THREADS (WARPS * 32)      // 128
#define FPB     (WARPS * FPW)     // 16 frames per block
#define FSTRIDE 198               // floats per frame region: 16 pad | 160 | 16 pad | 6 slack
#define PSTRIDE 99                // float2 pairs per frame region (odd -> conflict-free LDS.64)

typedef unsigned long long u64;

__device__ __forceinline__ u64 pack2(float lo, float hi) {
    u64 r; asm("mov.b64 %0, {%1, %2};" : "=l"(r) : "f"(lo), "f"(hi));
    return r;
}
#define BAR_SYNC(id)   asm volatile("bar.sync %0, %1;"   :: "r"(id), "r"(THREADS) : "memory")
#define BAR_ARRIVE(id) asm volatile("bar.arrive %0, %1;" :: "r"(id), "r"(THREADS) : "memory")

__global__ __launch_bounds__(THREADS, 8)
void lpc_residual_kernel(const float* __restrict__ x,
                         float* __restrict__ out,
                         int nframes)
{
    __shared__ __align__(16) float sx[WARPS * FPW * FSTRIDE];   // 12672 B
    __shared__ float rH[2][32][17];     // two 4-lane autocorr partials per frame (lane-safe size)
    __shared__ float aS[32][17];        // LPC coeffs per frame (lane-safe size)

    const int lane   = threadIdx.x & 31;
    const int wid    = threadIdx.x >> 5;
    const int frame0 = blockIdx.x * FPB + wid * FPW;            // this warp's first frame

    float* sw  = sx + wid * FPW * FSTRIDE;
    u64*   swp = (u64*)sw;

    // ---- zero pads: per frame, floats [0,16) and [176,192) => pairs [0,8) and [88,96) ----
    {
        int f = lane >> 3, c = lane & 7;
        swp[f * PSTRIDE + c]      = 0ull;
        swp[f * PSTRIDE + 88 + c] = 0ull;
    }

    // ---- stage input: 10x LDG.64 + 10x STS.64 per lane, coalesced & conflict-free ----
    {
        const float2* gx2 = (const float2*)(x + (long long)frame0 * FRAME);
        #pragma unroll
        for (int q = 0; q < 10; q++) {
            int idx = q * 32 + lane;               // float2 index within warp's 320
            int f;
            if (q == 2)      f = (lane < 16) ? 0 : 1;   // frame boundary crossings
            else if (q == 7) f = (lane < 16) ? 2 : 3;
            else             f = (q * 32) / 80;         // compile-time constant
            if (frame0 + f < nframes) {
                float2 v = gx2[idx];
                // shared pair index: f*99 + 8 + (idx - 80f) = idx + 8 + 19f
                swp[idx + 8 + 19 * f] = pack2(v.x, v.y);
            }
        }
    }
    __syncwarp();   // warp only reads its own staged frames below

    const int fl = lane >> 3;               // frame within warp (0..3)
    const int p  = lane & 7;                // sub-lane within frame (0..7)
    const int myFrame = wid * FPW + fl;     // frame index within block
    // pair index of float w[0] = x[20p] of this frame (float idx fl*198 + 16 + 20p)
    const int ubase = fl * PSTRIDE + 8 + 10 * p;
    const float2* swp2 = (const float2*)swp;

    // ---- autocorr: load w[0..35] (18 LDS.64), r[k] = sum_m w[m] w[m+k], 2-stage butterfly ----
    {
        float w[36];
        #pragma unroll
        for (int j = 0; j < 18; j++) {
            float2 t = swp2[ubase + j];
            w[2 * j] = t.x; w[2 * j + 1] = t.y;
        }
        #pragma unroll
        for (int k = 0; k <= ORDER; k++) {
            float acc = 0.0f;
            #pragma unroll
            for (int m = 0; m < 20; m++)
                acc = fmaf(w[m], w[m + k], acc);
            acc += __shfl_xor_sync(0xFFFFFFFFu, acc, 1);
            acc += __shfl_xor_sync(0xFFFFFFFFu, acc, 2);
            if ((p & 3) == 0) rH[p >> 2][myFrame][k] = acc;   // lanes p=0,4 store partials
        }
    }

    if (wid == 0) {
        // ---- consumer: wait for all partials, run Levinson (one frame per lane) ----
        BAR_SYNC(1);

        float rr[ORDER + 1];
        #pragma unroll
        for (int k = 0; k <= ORDER; k++)
            rr[k] = rH[0][lane][k] + rH[1][lane][k];

        float a[ORDER + 1];
        a[0] = 1.0f;
        float e = (rr[0] != 0.0f) ? rr[0] : EPS;
        #pragma unroll
        for (int i = 1; i <= ORDER; i++) {
            // acc = r[i] - sum_{j=1}^{i-1} a[j] r[i-j], 4-way split tree (short dep chain)
            float s0 = 0.f, s1 = 0.f, s2 = 0.f, s3 = 0.f;
            #pragma unroll
            for (int j = 1; j < i; j++) {
                float t = a[j] * 1.0f;  // keep simple; product below
                (void)t;
                switch ((j - 1) & 3) {
                    case 0: s0 = fmaf(a[j], rr[i - j], s0); break;
                    case 1: s1 = fmaf(a[j], rr[i - j], s1); break;
                    case 2: s2 = fmaf(a[j], rr[i - j], s2); break;
                    default: s3 = fmaf(a[j], rr[i - j], s3); break;
                }
            }
            float acc = rr[i] - ((s0 + s1) + (s2 + s3));
            float kk = __fdividef(acc, e);
            float tn[ORDER + 1];
            #pragma unroll
            for (int j = 1; j < i; j++)
                tn[j] = fmaf(-kk, a[i - j], a[j]);
            #pragma unroll
            for (int j = 1; j < i; j++)
                a[j] = tn[j];
            a[i] = kk;
            e = fmaxf(fmaf(-kk, acc, e), EPS);   // e*(1-k^2) = e - k*acc
        }
        #pragma unroll
        for (int k = 1; k <= ORDER; k++) aS[lane][k] = a[k];

        BAR_ARRIVE(2);
        __syncwarp();       // make warp-0's own aS stores visible to its other lanes
    } else {
        BAR_ARRIVE(1);      // partials published; don't wait for Levinson to start
    }

    // ---- FIR window w[-16..19] via 18 LDS.64 (prefetched under Levinson for warps 1-3) ----
    float v[36];
    #pragma unroll
    for (int j = 0; j < 18; j++) {
        float2 t = swp2[ubase - 8 + j];
        v[2 * j] = t.x; v[2 * j + 1] = t.y;
    }

    if (wid != 0) BAR_SYNC(2);   // wait for coefficients

    // ---- broadcast coeffs (8-lane broadcast per frame, conflict-free) ----
    float a[ORDER + 1];
    #pragma unroll
    for (int k = 1; k <= ORDER; k++) a[k] = aS[myFrame][k];

    // ---- FIR: res[n] = w[n] + sum_{k=1}^{16} a[k] * w[n-k]; store as float4 groups ----
    const bool wr = (frame0 + fl) < nframes;
    float4* go4 = (float4*)(out + (long long)(frame0 + fl) * FRAME + 20 * p);

    #pragma unroll
    for (int g = 0; g < 5; g++) {
        float res[4];
        #pragma unroll
        for (int h = 0; h < 4; h++) {
            int m = 16 + 4 * g + h;            // v index of output sample
            float s = v[m];                    // a[0] = 1 term
            #pragma unroll
            for (int k = 1; k <= ORDER; k++)
                s = fmaf(a[k], v[m - k], s);
            res[h] = s;
        }
        if (wr) go4[g] = make_float4(res[0], res[1], res[2], res[3]);
    }
}

extern "C" void kernel_launch(void* const* d_in, const int* in_sizes, int n_in,
                              void* d_out, int out_size)
{
    const float* x = (const float*)d_in[0];
    float* out = (float*)d_out;

    long long total = in_sizes[0];
    int nframes = (int)(total / FRAME);                 // 128000 for the given shape
    int blocks  = (nframes + FPB - 1) / FPB;            // 8000

    lpc_residual_kernel<<<blocks, THREADS>>>(x, out, nframes);
}